// round 5
// baseline (speedup 1.0000x reference)
#include <cuda_runtime.h>
#include <math.h>

#define B_   8
#define D_   256
#define TC_  2048
#define TE_  2048
#define TGT_ 256

// Scratch (allocation-free rule: __device__ globals)
__device__ float g_attn[(size_t)B_ * TC_ * TE_];   // sim -> attn in place (134 MB)
__device__ float g_wT[(size_t)B_ * D_ * TC_];      // weighted_emo, stored [B, D, Tc] (16 MB)

// ---------------------------------------------------------------------------
// GEMM1: sim[b,t,s] = sum_d content[b,d,t] * emotion[b,d,s]
// content: [B, D, TC] row-major (t contiguous); emotion: [B, D, TE] (s contiguous)
// Classic 128x128x8 SGEMM, 256 threads, 8x8 per thread.
// ---------------------------------------------------------------------------
__global__ __launch_bounds__(256, 2)
void gemm1_kernel(const float* __restrict__ content,
                  const float* __restrict__ emotion) {
    const int bb = blockIdx.z;
    const int t0 = blockIdx.y * 128;
    const int s0 = blockIdx.x * 128;
    const float* A = content + (size_t)bb * D_ * TC_;
    const float* Bm = emotion + (size_t)bb * D_ * TE_;
    float* C = g_attn + (size_t)bb * TC_ * TE_;

    __shared__ float As[8][128];
    __shared__ float Bs[8][128];

    const int tid = threadIdx.x;
    const int tx = tid & 15;          // s dir
    const int ty = tid >> 4;          // t dir
    const int lrow = tid >> 5;        // 0..7
    const int lcol = (tid & 31) * 4;  // 0..124

    float acc[8][8];
#pragma unroll
    for (int i = 0; i < 8; i++)
#pragma unroll
        for (int j = 0; j < 8; j++) acc[i][j] = 0.f;

    for (int k0 = 0; k0 < D_; k0 += 8) {
        float4 a4 = *reinterpret_cast<const float4*>(&A[(size_t)(k0 + lrow) * TC_ + t0 + lcol]);
        float4 b4 = *reinterpret_cast<const float4*>(&Bm[(size_t)(k0 + lrow) * TE_ + s0 + lcol]);
        *reinterpret_cast<float4*>(&As[lrow][lcol]) = a4;
        *reinterpret_cast<float4*>(&Bs[lrow][lcol]) = b4;
        __syncthreads();
#pragma unroll
        for (int kk = 0; kk < 8; kk++) {
            float4 a0 = *reinterpret_cast<const float4*>(&As[kk][ty * 8]);
            float4 a1 = *reinterpret_cast<const float4*>(&As[kk][ty * 8 + 4]);
            float4 b0 = *reinterpret_cast<const float4*>(&Bs[kk][tx * 8]);
            float4 b1 = *reinterpret_cast<const float4*>(&Bs[kk][tx * 8 + 4]);
            float ra[8] = {a0.x, a0.y, a0.z, a0.w, a1.x, a1.y, a1.z, a1.w};
            float rb[8] = {b0.x, b0.y, b0.z, b0.w, b1.x, b1.y, b1.z, b1.w};
#pragma unroll
            for (int i = 0; i < 8; i++)
#pragma unroll
                for (int j = 0; j < 8; j++) acc[i][j] = fmaf(ra[i], rb[j], acc[i][j]);
        }
        __syncthreads();
    }

#pragma unroll
    for (int i = 0; i < 8; i++) {
        float* crow = &C[(size_t)(t0 + ty * 8 + i) * TE_ + s0 + tx * 8];
        float4 v0 = {acc[i][0], acc[i][1], acc[i][2], acc[i][3]};
        float4 v1 = {acc[i][4], acc[i][5], acc[i][6], acc[i][7]};
        *reinterpret_cast<float4*>(crow) = v0;
        *reinterpret_cast<float4*>(crow + 4) = v1;
    }
}

// ---------------------------------------------------------------------------
// Softmax over s (2048), with 1/16 logit scale, in place on g_attn.
// One block (256 threads) per row; each thread owns 8 consecutive elements.
// ---------------------------------------------------------------------------
__global__ __launch_bounds__(256)
void softmax_kernel() {
    const size_t r = blockIdx.x;
    float* row = g_attn + r * (size_t)TE_;
    const int tid = threadIdx.x;
    const int lane = tid & 31, wid = tid >> 5;

    float4 v0 = reinterpret_cast<float4*>(row)[tid * 2];
    float4 v1 = reinterpret_cast<float4*>(row)[tid * 2 + 1];
    float v[8] = {v0.x, v0.y, v0.z, v0.w, v1.x, v1.y, v1.z, v1.w};

    float m = v[0];
#pragma unroll
    for (int q = 1; q < 8; q++) m = fmaxf(m, v[q]);
#pragma unroll
    for (int o = 16; o > 0; o >>= 1) m = fmaxf(m, __shfl_xor_sync(0xffffffffu, m, o));

    __shared__ float smax[8];
    __shared__ float ssum[8];
    if (lane == 0) smax[wid] = m;
    __syncthreads();
    if (tid < 32) {
        float t = (lane < 8) ? smax[lane] : -INFINITY;
#pragma unroll
        for (int o = 4; o > 0; o >>= 1) t = fmaxf(t, __shfl_xor_sync(0xffffffffu, t, o));
        if (lane == 0) smax[0] = t;
    }
    __syncthreads();
    const float bm = smax[0];

    float s = 0.f;
#pragma unroll
    for (int q = 0; q < 8; q++) {
        v[q] = expf((v[q] - bm) * 0.0625f);
        s += v[q];
    }
#pragma unroll
    for (int o = 16; o > 0; o >>= 1) s += __shfl_xor_sync(0xffffffffu, s, o);
    if (lane == 0) ssum[wid] = s;
    __syncthreads();
    if (tid < 32) {
        float t = (lane < 8) ? ssum[lane] : 0.f;
#pragma unroll
        for (int o = 4; o > 0; o >>= 1) t += __shfl_xor_sync(0xffffffffu, t, o);
        if (lane == 0) ssum[0] = t;
    }
    __syncthreads();
    const float inv = 1.f / ssum[0];

    float4 o0 = {v[0] * inv, v[1] * inv, v[2] * inv, v[3] * inv};
    float4 o1 = {v[4] * inv, v[5] * inv, v[6] * inv, v[7] * inv};
    reinterpret_cast<float4*>(row)[tid * 2] = o0;
    reinterpret_cast<float4*>(row)[tid * 2 + 1] = o1;
}

// ---------------------------------------------------------------------------
// GEMM2: wT[b,d,t] = sum_s emotion[b,d,s] * attn[b,t,s]   ("NT" gemm)
// Tile: 64 (d) x 128 (t) x 16 (s). 256 threads, 4x8 per thread.
// ---------------------------------------------------------------------------
__global__ __launch_bounds__(256, 2)
void gemm2_kernel(const float* __restrict__ emotion) {
    const int bb = blockIdx.z;
    const int d0 = blockIdx.y * 64;
    const int t0 = blockIdx.x * 128;
    const float* E = emotion + (size_t)bb * D_ * TE_;
    const float* At = g_attn + (size_t)bb * TC_ * TE_;
    float* C = g_wT + (size_t)bb * D_ * TC_;

    __shared__ float As[16][68];   // [s][d], pad keeps rows 16B-aligned
    __shared__ float Bs[16][132];  // [s][t]

    const int tid = threadIdx.x;
    const int tx = tid & 15;   // t dir (8 each)
    const int ty = tid >> 4;   // d dir (4 each)

    const int add = tid >> 2;           // 0..63
    const int akq = (tid & 3) * 4;      // 0,4,8,12
    const int btt = tid >> 1;           // 0..127
    const int bkq = (tid & 1) * 8;      // 0 or 8

    float acc[4][8];
#pragma unroll
    for (int i = 0; i < 4; i++)
#pragma unroll
        for (int j = 0; j < 8; j++) acc[i][j] = 0.f;

    for (int s0 = 0; s0 < TE_; s0 += 16) {
        float4 a4 = *reinterpret_cast<const float4*>(&E[(size_t)(d0 + add) * TE_ + s0 + akq]);
        As[akq + 0][add] = a4.x;
        As[akq + 1][add] = a4.y;
        As[akq + 2][add] = a4.z;
        As[akq + 3][add] = a4.w;

        const float* brow = &At[(size_t)(t0 + btt) * TE_ + s0 + bkq];
        float4 b4a = *reinterpret_cast<const float4*>(brow);
        float4 b4b = *reinterpret_cast<const float4*>(brow + 4);
        Bs[bkq + 0][btt] = b4a.x;
        Bs[bkq + 1][btt] = b4a.y;
        Bs[bkq + 2][btt] = b4a.z;
        Bs[bkq + 3][btt] = b4a.w;
        Bs[bkq + 4][btt] = b4b.x;
        Bs[bkq + 5][btt] = b4b.y;
        Bs[bkq + 6][btt] = b4b.z;
        Bs[bkq + 7][btt] = b4b.w;
        __syncthreads();

#pragma unroll
        for (int kk = 0; kk < 16; kk++) {
            float4 ra4 = *reinterpret_cast<const float4*>(&As[kk][ty * 4]);
            float4 rb0 = *reinterpret_cast<const float4*>(&Bs[kk][tx * 8]);
            float4 rb1 = *reinterpret_cast<const float4*>(&Bs[kk][tx * 8 + 4]);
            float ra[4] = {ra4.x, ra4.y, ra4.z, ra4.w};
            float rb[8] = {rb0.x, rb0.y, rb0.z, rb0.w, rb1.x, rb1.y, rb1.z, rb1.w};
#pragma unroll
            for (int i = 0; i < 4; i++)
#pragma unroll
                for (int j = 0; j < 8; j++) acc[i][j] = fmaf(ra[i], rb[j], acc[i][j]);
        }
        __syncthreads();
    }

#pragma unroll
    for (int i = 0; i < 4; i++) {
        float* crow = &C[(size_t)(d0 + ty * 4 + i) * TC_ + t0 + tx * 8];
        float4 v0 = {acc[i][0], acc[i][1], acc[i][2], acc[i][3]};
        float4 v1 = {acc[i][4], acc[i][5], acc[i][6], acc[i][7]};
        *reinterpret_cast<float4*>(crow) = v0;
        *reinterpret_cast<float4*>(crow + 4) = v1;
    }
}

// ---------------------------------------------------------------------------
// Conv1d k=3 pad=1: out[b,o,t] = bias[o] + sum_{i<512} sum_tap w[o,i,tap]*x[b,i,t+tap-1]
// x[b,i,t] = (i<256) ? content[b,i,t] : g_wT[b,i-256,t]  (virtual concat)
// Tile: 64 (o) x 128 (t), K-chunks of 16 channels.
// ---------------------------------------------------------------------------
__global__ __launch_bounds__(256, 2)
void conv_kernel(const float* __restrict__ content,
                 const float* __restrict__ conv_w,
                 const float* __restrict__ conv_b,
                 float* __restrict__ out) {
    const int bb = blockIdx.z;
    const int o0 = blockIdx.y * 64;
    const int t0 = blockIdx.x * 128;

    __shared__ float Ws[64][48];    // [oo][ii*3+tap]
    __shared__ float Xs[16][132];   // [ii][tt], tt=0 <-> t0-1, 130 used

    const int tid = threadIdx.x;
    const int tx = tid & 15;  // t dir (8 each)
    const int ty = tid >> 4;  // o dir (4 each)

    const int woo = tid >> 2;          // 0..63
    const int wc0 = (tid & 3) * 12;    // 0,12,24,36

    float acc[4][8];
#pragma unroll
    for (int i = 0; i < 4; i++)
#pragma unroll
        for (int j = 0; j < 8; j++) acc[i][j] = 0.f;

    for (int i0 = 0; i0 < 2 * D_; i0 += 16) {
        // weights: 48 contiguous floats per output channel row
        const float* wrow = conv_w + (size_t)(o0 + woo) * (2 * D_ * 3) + (size_t)i0 * 3 + wc0;
#pragma unroll
        for (int q = 0; q < 3; q++)
            *reinterpret_cast<float4*>(&Ws[woo][wc0 + q * 4]) =
                *reinterpret_cast<const float4*>(&wrow[q * 4]);

        // input tile with halo
        for (int idx = tid; idx < 16 * 130; idx += 256) {
            const int ii = idx / 130;
            const int tt = idx - ii * 130;
            const int t = t0 + tt - 1;
            const int gi = i0 + ii;
            float v = 0.f;
            if (t >= 0 && t < TC_) {
                v = (gi < D_) ? content[((size_t)bb * D_ + gi) * TC_ + t]
                              : g_wT[((size_t)bb * D_ + (gi - D_)) * TC_ + t];
            }
            Xs[ii][tt] = v;
        }
        __syncthreads();

#pragma unroll
        for (int ii = 0; ii < 16; ii++) {
            float xr[10];
#pragma unroll
            for (int q = 0; q < 10; q++) xr[q] = Xs[ii][tx * 8 + q];
#pragma unroll
            for (int i = 0; i < 4; i++) {
                const float w0 = Ws[ty * 4 + i][ii * 3 + 0];
                const float w1 = Ws[ty * 4 + i][ii * 3 + 1];
                const float w2 = Ws[ty * 4 + i][ii * 3 + 2];
#pragma unroll
                for (int j = 0; j < 8; j++) {
                    acc[i][j] = fmaf(w0, xr[j], acc[i][j]);
                    acc[i][j] = fmaf(w1, xr[j + 1], acc[i][j]);
                    acc[i][j] = fmaf(w2, xr[j + 2], acc[i][j]);
                }
            }
        }
        __syncthreads();
    }

#pragma unroll
    for (int i = 0; i < 4; i++) {
        const int o = o0 + ty * 4 + i;
        const float bv = __ldg(&conv_b[o]);
        float* orow = out + ((size_t)bb * TGT_ + o) * TC_ + t0 + tx * 8;
        float4 v0 = {acc[i][0] + bv, acc[i][1] + bv, acc[i][2] + bv, acc[i][3] + bv};
        float4 v1 = {acc[i][4] + bv, acc[i][5] + bv, acc[i][6] + bv, acc[i][7] + bv};
        *reinterpret_cast<float4*>(orow) = v0;
        *reinterpret_cast<float4*>(orow + 4) = v1;
    }
}

// ---------------------------------------------------------------------------
extern "C" void kernel_launch(void* const* d_in, const int* in_sizes, int n_in,
                              void* d_out, int out_size) {
    const float* content = (const float*)d_in[0];  // [8,256,2048]
    const float* emotion = (const float*)d_in[1];  // [8,256,2048]
    const float* conv_w  = (const float*)d_in[2];  // [256,512,3]
    const float* conv_b  = (const float*)d_in[3];  // [256]
    float* out = (float*)d_out;                    // [8,256,2048]

    dim3 g1(TE_ / 128, TC_ / 128, B_);
    gemm1_kernel<<<g1, 256>>>(content, emotion);

    softmax_kernel<<<B_ * TC_, 256>>>();

    dim3 g2(TC_ / 128, D_ / 64, B_);
    gemm2_kernel<<<g2, 256>>>(emotion);

    dim3 g3(TC_ / 128, TGT_ / 64, B_);
    conv_kernel<<<g3, 256>>>(content, conv_w, conv_b, out);
}

// round 6
// speedup vs baseline: 1.0488x; 1.0488x over previous
#include <cuda_runtime.h>
#include <math.h>

#define B_   8
#define D_   256
#define TC_  2048
#define TE_  2048
#define TGT_ 256

// Scratch (allocation-free rule: __device__ globals)
__device__ float g_attn[(size_t)B_ * TC_ * TE_];   // sim -> attn in place (134 MB)
__device__ float g_wT[(size_t)B_ * D_ * TC_];      // weighted_emo, stored [B, D, Tc] (16 MB)

// ---------------------------------------------------------------------------
// GEMM1: sim[b,t,s] = sum_d content[b,d,t] * emotion[b,d,s]
// content: [B, D, TC] row-major (t contiguous); emotion: [B, D, TE] (s contiguous)
// Classic 128x128x8 SGEMM, 256 threads, 8x8 per thread.
// ---------------------------------------------------------------------------
__global__ __launch_bounds__(256, 2)
void gemm1_kernel(const float* __restrict__ content,
                  const float* __restrict__ emotion) {
    const int bb = blockIdx.z;
    const int t0 = blockIdx.y * 128;
    const int s0 = blockIdx.x * 128;
    const float* A = content + (size_t)bb * D_ * TC_;
    const float* Bm = emotion + (size_t)bb * D_ * TE_;
    float* C = g_attn + (size_t)bb * TC_ * TE_;

    __shared__ float As[8][128];
    __shared__ float Bs[8][128];

    const int tid = threadIdx.x;
    const int tx = tid & 15;          // s dir
    const int ty = tid >> 4;          // t dir
    const int lrow = tid >> 5;        // 0..7
    const int lcol = (tid & 31) * 4;  // 0..124

    float acc[8][8];
#pragma unroll
    for (int i = 0; i < 8; i++)
#pragma unroll
        for (int j = 0; j < 8; j++) acc[i][j] = 0.f;

    for (int k0 = 0; k0 < D_; k0 += 8) {
        float4 a4 = *reinterpret_cast<const float4*>(&A[(size_t)(k0 + lrow) * TC_ + t0 + lcol]);
        float4 b4 = *reinterpret_cast<const float4*>(&Bm[(size_t)(k0 + lrow) * TE_ + s0 + lcol]);
        *reinterpret_cast<float4*>(&As[lrow][lcol]) = a4;
        *reinterpret_cast<float4*>(&Bs[lrow][lcol]) = b4;
        __syncthreads();
#pragma unroll
        for (int kk = 0; kk < 8; kk++) {
            float4 a0 = *reinterpret_cast<const float4*>(&As[kk][ty * 8]);
            float4 a1 = *reinterpret_cast<const float4*>(&As[kk][ty * 8 + 4]);
            float4 b0 = *reinterpret_cast<const float4*>(&Bs[kk][tx * 8]);
            float4 b1 = *reinterpret_cast<const float4*>(&Bs[kk][tx * 8 + 4]);
            float ra[8] = {a0.x, a0.y, a0.z, a0.w, a1.x, a1.y, a1.z, a1.w};
            float rb[8] = {b0.x, b0.y, b0.z, b0.w, b1.x, b1.y, b1.z, b1.w};
#pragma unroll
            for (int i = 0; i < 8; i++)
#pragma unroll
                for (int j = 0; j < 8; j++) acc[i][j] = fmaf(ra[i], rb[j], acc[i][j]);
        }
        __syncthreads();
    }

#pragma unroll
    for (int i = 0; i < 8; i++) {
        float* crow = &C[(size_t)(t0 + ty * 8 + i) * TE_ + s0 + tx * 8];
        float4 v0 = {acc[i][0], acc[i][1], acc[i][2], acc[i][3]};
        float4 v1 = {acc[i][4], acc[i][5], acc[i][6], acc[i][7]};
        *reinterpret_cast<float4*>(crow) = v0;
        *reinterpret_cast<float4*>(crow + 4) = v1;
    }
}

// ---------------------------------------------------------------------------
// Softmax over s (2048), with 1/16 logit scale, in place on g_attn.
// One block (256 threads) per row; each thread owns 8 consecutive elements.
// ---------------------------------------------------------------------------
__global__ __launch_bounds__(256)
void softmax_kernel() {
    const size_t r = blockIdx.x;
    float* row = g_attn + r * (size_t)TE_;
    const int tid = threadIdx.x;
    const int lane = tid & 31, wid = tid >> 5;

    float4 v0 = reinterpret_cast<float4*>(row)[tid * 2];
    float4 v1 = reinterpret_cast<float4*>(row)[tid * 2 + 1];
    float v[8] = {v0.x, v0.y, v0.z, v0.w, v1.x, v1.y, v1.z, v1.w};

    float m = v[0];
#pragma unroll
    for (int q = 1; q < 8; q++) m = fmaxf(m, v[q]);
#pragma unroll
    for (int o = 16; o > 0; o >>= 1) m = fmaxf(m, __shfl_xor_sync(0xffffffffu, m, o));

    __shared__ float smax[8];
    __shared__ float ssum[8];
    if (lane == 0) smax[wid] = m;
    __syncthreads();
    if (tid < 32) {
        float t = (lane < 8) ? smax[lane] : -INFINITY;
#pragma unroll
        for (int o = 4; o > 0; o >>= 1) t = fmaxf(t, __shfl_xor_sync(0xffffffffu, t, o));
        if (lane == 0) smax[0] = t;
    }
    __syncthreads();
    const float bm = smax[0];

    float s = 0.f;
#pragma unroll
    for (int q = 0; q < 8; q++) {
        v[q] = expf((v[q] - bm) * 0.0625f);
        s += v[q];
    }
#pragma unroll
    for (int o = 16; o > 0; o >>= 1) s += __shfl_xor_sync(0xffffffffu, s, o);
    if (lane == 0) ssum[wid] = s;
    __syncthreads();
    if (tid < 32) {
        float t = (lane < 8) ? ssum[lane] : 0.f;
#pragma unroll
        for (int o = 4; o > 0; o >>= 1) t += __shfl_xor_sync(0xffffffffu, t, o);
        if (lane == 0) ssum[0] = t;
    }
    __syncthreads();
    const float inv = 1.f / ssum[0];

    float4 o0 = {v[0] * inv, v[1] * inv, v[2] * inv, v[3] * inv};
    float4 o1 = {v[4] * inv, v[5] * inv, v[6] * inv, v[7] * inv};
    reinterpret_cast<float4*>(row)[tid * 2] = o0;
    reinterpret_cast<float4*>(row)[tid * 2 + 1] = o1;
}

// ---------------------------------------------------------------------------
// GEMM2: wT[b,d,t] = sum_s emotion[b,d,s] * attn[b,t,s]   ("NT" gemm)
// Tile: 64 (d) x 128 (t) x 16 (s). 256 threads, 4x8 per thread.
// ---------------------------------------------------------------------------
__global__ __launch_bounds__(256, 2)
void gemm2_kernel(const float* __restrict__ emotion) {
    const int bb = blockIdx.z;
    const int d0 = blockIdx.y * 64;
    const int t0 = blockIdx.x * 128;
    const float* E = emotion + (size_t)bb * D_ * TE_;
    const float* At = g_attn + (size_t)bb * TC_ * TE_;
    float* C = g_wT + (size_t)bb * D_ * TC_;

    __shared__ float As[16][68];   // [s][d], pad keeps rows 16B-aligned
    __shared__ float Bs[16][132];  // [s][t]

    const int tid = threadIdx.x;
    const int tx = tid & 15;   // t dir (8 each)
    const int ty = tid >> 4;   // d dir (4 each)

    const int add = tid >> 2;           // 0..63
    const int akq = (tid & 3) * 4;      // 0,4,8,12
    const int btt = tid >> 1;           // 0..127
    const int bkq = (tid & 1) * 8;      // 0 or 8

    float acc[4][8];
#pragma unroll
    for (int i = 0; i < 4; i++)
#pragma unroll
        for (int j = 0; j < 8; j++) acc[i][j] = 0.f;

    for (int s0 = 0; s0 < TE_; s0 += 16) {
        float4 a4 = *reinterpret_cast<const float4*>(&E[(size_t)(d0 + add) * TE_ + s0 + akq]);
        As[akq + 0][add] = a4.x;
        As[akq + 1][add] = a4.y;
        As[akq + 2][add] = a4.z;
        As[akq + 3][add] = a4.w;

        const float* brow = &At[(size_t)(t0 + btt) * TE_ + s0 + bkq];
        float4 b4a = *reinterpret_cast<const float4*>(brow);
        float4 b4b = *reinterpret_cast<const float4*>(brow + 4);
        Bs[bkq + 0][btt] = b4a.x;
        Bs[bkq + 1][btt] = b4a.y;
        Bs[bkq + 2][btt] = b4a.z;
        Bs[bkq + 3][btt] = b4a.w;
        Bs[bkq + 4][btt] = b4b.x;
        Bs[bkq + 5][btt] = b4b.y;
        Bs[bkq + 6][btt] = b4b.z;
        Bs[bkq + 7][btt] = b4b.w;
        __syncthreads();

#pragma unroll
        for (int kk = 0; kk < 16; kk++) {
            float4 ra4 = *reinterpret_cast<const float4*>(&As[kk][ty * 4]);
            float4 rb0 = *reinterpret_cast<const float4*>(&Bs[kk][tx * 8]);
            float4 rb1 = *reinterpret_cast<const float4*>(&Bs[kk][tx * 8 + 4]);
            float ra[4] = {ra4.x, ra4.y, ra4.z, ra4.w};
            float rb[8] = {rb0.x, rb0.y, rb0.z, rb0.w, rb1.x, rb1.y, rb1.z, rb1.w};
#pragma unroll
            for (int i = 0; i < 4; i++)
#pragma unroll
                for (int j = 0; j < 8; j++) acc[i][j] = fmaf(ra[i], rb[j], acc[i][j]);
        }
        __syncthreads();
    }

#pragma unroll
    for (int i = 0; i < 4; i++) {
        float* crow = &C[(size_t)(d0 + ty * 4 + i) * TC_ + t0 + tx * 8];
        float4 v0 = {acc[i][0], acc[i][1], acc[i][2], acc[i][3]};
        float4 v1 = {acc[i][4], acc[i][5], acc[i][6], acc[i][7]};
        *reinterpret_cast<float4*>(crow) = v0;
        *reinterpret_cast<float4*>(crow + 4) = v1;
    }
}

// ---------------------------------------------------------------------------
// Conv1d k=3 pad=1: out[b,o,t] = bias[o] + sum_{i<512} sum_tap w[o,i,tap]*x[b,i,t+tap-1]
// x[b,i,t] = (i<256) ? content[b,i,t] : g_wT[b,i-256,t]  (virtual concat)
// Tile: 64 (o) x 128 (t), K-chunks of 16 channels.
// ---------------------------------------------------------------------------
__global__ __launch_bounds__(256, 2)
void conv_kernel(const float* __restrict__ content,
                 const float* __restrict__ conv_w,
                 const float* __restrict__ conv_b,
                 float* __restrict__ out) {
    const int bb = blockIdx.z;
    const int o0 = blockIdx.y * 64;
    const int t0 = blockIdx.x * 128;

    __shared__ float Ws[64][48];    // [oo][ii*3+tap]
    __shared__ float Xs[16][132];   // [ii][tt], tt=0 <-> t0-1, 130 used

    const int tid = threadIdx.x;
    const int tx = tid & 15;  // t dir (8 each)
    const int ty = tid >> 4;  // o dir (4 each)

    const int woo = tid >> 2;          // 0..63
    const int wc0 = (tid & 3) * 12;    // 0,12,24,36

    float acc[4][8];
#pragma unroll
    for (int i = 0; i < 4; i++)
#pragma unroll
        for (int j = 0; j < 8; j++) acc[i][j] = 0.f;

    for (int i0 = 0; i0 < 2 * D_; i0 += 16) {
        // weights: 48 contiguous floats per output channel row
        const float* wrow = conv_w + (size_t)(o0 + woo) * (2 * D_ * 3) + (size_t)i0 * 3 + wc0;
#pragma unroll
        for (int q = 0; q < 3; q++)
            *reinterpret_cast<float4*>(&Ws[woo][wc0 + q * 4]) =
                *reinterpret_cast<const float4*>(&wrow[q * 4]);

        // input tile with halo
        for (int idx = tid; idx < 16 * 130; idx += 256) {
            const int ii = idx / 130;
            const int tt = idx - ii * 130;
            const int t = t0 + tt - 1;
            const int gi = i0 + ii;
            float v = 0.f;
            if (t >= 0 && t < TC_) {
                v = (gi < D_) ? content[((size_t)bb * D_ + gi) * TC_ + t]
                              : g_wT[((size_t)bb * D_ + (gi - D_)) * TC_ + t];
            }
            Xs[ii][tt] = v;
        }
        __syncthreads();

#pragma unroll
        for (int ii = 0; ii < 16; ii++) {
            float xr[10];
#pragma unroll
            for (int q = 0; q < 10; q++) xr[q] = Xs[ii][tx * 8 + q];
#pragma unroll
            for (int i = 0; i < 4; i++) {
                const float w0 = Ws[ty * 4 + i][ii * 3 + 0];
                const float w1 = Ws[ty * 4 + i][ii * 3 + 1];
                const float w2 = Ws[ty * 4 + i][ii * 3 + 2];
#pragma unroll
                for (int j = 0; j < 8; j++) {
                    acc[i][j] = fmaf(w0, xr[j], acc[i][j]);
                    acc[i][j] = fmaf(w1, xr[j + 1], acc[i][j]);
                    acc[i][j] = fmaf(w2, xr[j + 2], acc[i][j]);
                }
            }
        }
        __syncthreads();
    }

#pragma unroll
    for (int i = 0; i < 4; i++) {
        const int o = o0 + ty * 4 + i;
        const float bv = __ldg(&conv_b[o]);
        float* orow = out + ((size_t)bb * TGT_ + o) * TC_ + t0 + tx * 8;
        float4 v0 = {acc[i][0] + bv, acc[i][1] + bv, acc[i][2] + bv, acc[i][3] + bv};
        float4 v1 = {acc[i][4] + bv, acc[i][5] + bv, acc[i][6] + bv, acc[i][7] + bv};
        *reinterpret_cast<float4*>(orow) = v0;
        *reinterpret_cast<float4*>(orow + 4) = v1;
    }
}

// ---------------------------------------------------------------------------
extern "C" void kernel_launch(void* const* d_in, const int* in_sizes, int n_in,
                              void* d_out, int out_size) {
    const float* content = (const float*)d_in[0];  // [8,256,2048]
    const float* emotion = (const float*)d_in[1];  // [8,256,2048]
    const float* conv_w  = (const float*)d_in[2];  // [256,512,3]
    const float* conv_b  = (const float*)d_in[3];  // [256]
    float* out = (float*)d_out;                    // [8,256,2048]

    dim3 g1(TE_ / 128, TC_ / 128, B_);
    gemm1_kernel<<<g1, 256>>>(content, emotion);

    softmax_kernel<<<B_ * TC_, 256>>>();

    dim3 g2(TC_ / 128, D_ / 64, B_);
    gemm2_kernel<<<g2, 256>>>(emotion);

    dim3 g3(TC_ / 128, TGT_ / 64, B_);
    conv_kernel<<<g3, 256>>>(content, conv_w, conv_b, out);
}

// round 7
// speedup vs baseline: 1.0488x; 1.0001x over previous
#include <cuda_runtime.h>
#include <math.h>

#define B_   8
#define D_   256
#define TC_  2048
#define TE_  2048
#define TGT_ 256

// Scratch (allocation-free rule: __device__ globals)
__device__ float g_attn[(size_t)B_ * TC_ * TE_];   // sim -> attn in place (134 MB)
__device__ float g_wT[(size_t)B_ * D_ * TC_];      // weighted_emo, stored [B, D, Tc] (16 MB)

// ---------------------------------------------------------------------------
// GEMM1: sim[b,t,s] = sum_d content[b,d,t] * emotion[b,d,s]
// content: [B, D, TC] row-major (t contiguous); emotion: [B, D, TE] (s contiguous)
// Classic 128x128x8 SGEMM, 256 threads, 8x8 per thread.
// ---------------------------------------------------------------------------
__global__ __launch_bounds__(256, 2)
void gemm1_kernel(const float* __restrict__ content,
                  const float* __restrict__ emotion) {
    const int bb = blockIdx.z;
    const int t0 = blockIdx.y * 128;
    const int s0 = blockIdx.x * 128;
    const float* A = content + (size_t)bb * D_ * TC_;
    const float* Bm = emotion + (size_t)bb * D_ * TE_;
    float* C = g_attn + (size_t)bb * TC_ * TE_;

    __shared__ float As[8][128];
    __shared__ float Bs[8][128];

    const int tid = threadIdx.x;
    const int tx = tid & 15;          // s dir
    const int ty = tid >> 4;          // t dir
    const int lrow = tid >> 5;        // 0..7
    const int lcol = (tid & 31) * 4;  // 0..124

    float acc[8][8];
#pragma unroll
    for (int i = 0; i < 8; i++)
#pragma unroll
        for (int j = 0; j < 8; j++) acc[i][j] = 0.f;

    for (int k0 = 0; k0 < D_; k0 += 8) {
        float4 a4 = *reinterpret_cast<const float4*>(&A[(size_t)(k0 + lrow) * TC_ + t0 + lcol]);
        float4 b4 = *reinterpret_cast<const float4*>(&Bm[(size_t)(k0 + lrow) * TE_ + s0 + lcol]);
        *reinterpret_cast<float4*>(&As[lrow][lcol]) = a4;
        *reinterpret_cast<float4*>(&Bs[lrow][lcol]) = b4;
        __syncthreads();
#pragma unroll
        for (int kk = 0; kk < 8; kk++) {
            float4 a0 = *reinterpret_cast<const float4*>(&As[kk][ty * 8]);
            float4 a1 = *reinterpret_cast<const float4*>(&As[kk][ty * 8 + 4]);
            float4 b0 = *reinterpret_cast<const float4*>(&Bs[kk][tx * 8]);
            float4 b1 = *reinterpret_cast<const float4*>(&Bs[kk][tx * 8 + 4]);
            float ra[8] = {a0.x, a0.y, a0.z, a0.w, a1.x, a1.y, a1.z, a1.w};
            float rb[8] = {b0.x, b0.y, b0.z, b0.w, b1.x, b1.y, b1.z, b1.w};
#pragma unroll
            for (int i = 0; i < 8; i++)
#pragma unroll
                for (int j = 0; j < 8; j++) acc[i][j] = fmaf(ra[i], rb[j], acc[i][j]);
        }
        __syncthreads();
    }

#pragma unroll
    for (int i = 0; i < 8; i++) {
        float* crow = &C[(size_t)(t0 + ty * 8 + i) * TE_ + s0 + tx * 8];
        float4 v0 = {acc[i][0], acc[i][1], acc[i][2], acc[i][3]};
        float4 v1 = {acc[i][4], acc[i][5], acc[i][6], acc[i][7]};
        *reinterpret_cast<float4*>(crow) = v0;
        *reinterpret_cast<float4*>(crow + 4) = v1;
    }
}

// ---------------------------------------------------------------------------
// Softmax over s (2048), with 1/16 logit scale, in place on g_attn.
// One block (256 threads) per row; each thread owns 8 consecutive elements.
// ---------------------------------------------------------------------------
__global__ __launch_bounds__(256)
void softmax_kernel() {
    const size_t r = blockIdx.x;
    float* row = g_attn + r * (size_t)TE_;
    const int tid = threadIdx.x;
    const int lane = tid & 31, wid = tid >> 5;

    float4 v0 = reinterpret_cast<float4*>(row)[tid * 2];
    float4 v1 = reinterpret_cast<float4*>(row)[tid * 2 + 1];
    float v[8] = {v0.x, v0.y, v0.z, v0.w, v1.x, v1.y, v1.z, v1.w};

    float m = v[0];
#pragma unroll
    for (int q = 1; q < 8; q++) m = fmaxf(m, v[q]);
#pragma unroll
    for (int o = 16; o > 0; o >>= 1) m = fmaxf(m, __shfl_xor_sync(0xffffffffu, m, o));

    __shared__ float smax[8];
    __shared__ float ssum[8];
    if (lane == 0) smax[wid] = m;
    __syncthreads();
    if (tid < 32) {
        float t = (lane < 8) ? smax[lane] : -INFINITY;
#pragma unroll
        for (int o = 4; o > 0; o >>= 1) t = fmaxf(t, __shfl_xor_sync(0xffffffffu, t, o));
        if (lane == 0) smax[0] = t;
    }
    __syncthreads();
    const float bm = smax[0];

    float s = 0.f;
#pragma unroll
    for (int q = 0; q < 8; q++) {
        v[q] = expf((v[q] - bm) * 0.0625f);
        s += v[q];
    }
#pragma unroll
    for (int o = 16; o > 0; o >>= 1) s += __shfl_xor_sync(0xffffffffu, s, o);
    if (lane == 0) ssum[wid] = s;
    __syncthreads();
    if (tid < 32) {
        float t = (lane < 8) ? ssum[lane] : 0.f;
#pragma unroll
        for (int o = 4; o > 0; o >>= 1) t += __shfl_xor_sync(0xffffffffu, t, o);
        if (lane == 0) ssum[0] = t;
    }
    __syncthreads();
    const float inv = 1.f / ssum[0];

    float4 o0 = {v[0] * inv, v[1] * inv, v[2] * inv, v[3] * inv};
    float4 o1 = {v[4] * inv, v[5] * inv, v[6] * inv, v[7] * inv};
    reinterpret_cast<float4*>(row)[tid * 2] = o0;
    reinterpret_cast<float4*>(row)[tid * 2 + 1] = o1;
}

// ---------------------------------------------------------------------------
// GEMM2: wT[b,d,t] = sum_s emotion[b,d,s] * attn[b,t,s]   ("NT" gemm)
// Tile: 64 (d) x 128 (t) x 16 (s). 256 threads, 4x8 per thread.
// ---------------------------------------------------------------------------
__global__ __launch_bounds__(256, 2)
void gemm2_kernel(const float* __restrict__ emotion) {
    const int bb = blockIdx.z;
    const int d0 = blockIdx.y * 64;
    const int t0 = blockIdx.x * 128;
    const float* E = emotion + (size_t)bb * D_ * TE_;
    const float* At = g_attn + (size_t)bb * TC_ * TE_;
    float* C = g_wT + (size_t)bb * D_ * TC_;

    __shared__ float As[16][68];   // [s][d], pad keeps rows 16B-aligned
    __shared__ float Bs[16][132];  // [s][t]

    const int tid = threadIdx.x;
    const int tx = tid & 15;   // t dir (8 each)
    const int ty = tid >> 4;   // d dir (4 each)

    const int add = tid >> 2;           // 0..63
    const int akq = (tid & 3) * 4;      // 0,4,8,12
    const int btt = tid >> 1;           // 0..127
    const int bkq = (tid & 1) * 8;      // 0 or 8

    float acc[4][8];
#pragma unroll
    for (int i = 0; i < 4; i++)
#pragma unroll
        for (int j = 0; j < 8; j++) acc[i][j] = 0.f;

    for (int s0 = 0; s0 < TE_; s0 += 16) {
        float4 a4 = *reinterpret_cast<const float4*>(&E[(size_t)(d0 + add) * TE_ + s0 + akq]);
        As[akq + 0][add] = a4.x;
        As[akq + 1][add] = a4.y;
        As[akq + 2][add] = a4.z;
        As[akq + 3][add] = a4.w;

        const float* brow = &At[(size_t)(t0 + btt) * TE_ + s0 + bkq];
        float4 b4a = *reinterpret_cast<const float4*>(brow);
        float4 b4b = *reinterpret_cast<const float4*>(brow + 4);
        Bs[bkq + 0][btt] = b4a.x;
        Bs[bkq + 1][btt] = b4a.y;
        Bs[bkq + 2][btt] = b4a.z;
        Bs[bkq + 3][btt] = b4a.w;
        Bs[bkq + 4][btt] = b4b.x;
        Bs[bkq + 5][btt] = b4b.y;
        Bs[bkq + 6][btt] = b4b.z;
        Bs[bkq + 7][btt] = b4b.w;
        __syncthreads();

#pragma unroll
        for (int kk = 0; kk < 16; kk++) {
            float4 ra4 = *reinterpret_cast<const float4*>(&As[kk][ty * 4]);
            float4 rb0 = *reinterpret_cast<const float4*>(&Bs[kk][tx * 8]);
            float4 rb1 = *reinterpret_cast<const float4*>(&Bs[kk][tx * 8 + 4]);
            float ra[4] = {ra4.x, ra4.y, ra4.z, ra4.w};
            float rb[8] = {rb0.x, rb0.y, rb0.z, rb0.w, rb1.x, rb1.y, rb1.z, rb1.w};
#pragma unroll
            for (int i = 0; i < 4; i++)
#pragma unroll
                for (int j = 0; j < 8; j++) acc[i][j] = fmaf(ra[i], rb[j], acc[i][j]);
        }
        __syncthreads();
    }

#pragma unroll
    for (int i = 0; i < 4; i++) {
        float* crow = &C[(size_t)(d0 + ty * 4 + i) * TC_ + t0 + tx * 8];
        float4 v0 = {acc[i][0], acc[i][1], acc[i][2], acc[i][3]};
        float4 v1 = {acc[i][4], acc[i][5], acc[i][6], acc[i][7]};
        *reinterpret_cast<float4*>(crow) = v0;
        *reinterpret_cast<float4*>(crow + 4) = v1;
    }
}

// ---------------------------------------------------------------------------
// Conv1d k=3 pad=1: out[b,o,t] = bias[o] + sum_{i<512} sum_tap w[o,i,tap]*x[b,i,t+tap-1]
// x[b,i,t] = (i<256) ? content[b,i,t] : g_wT[b,i-256,t]  (virtual concat)
// Tile: 64 (o) x 128 (t), K-chunks of 16 channels.
// ---------------------------------------------------------------------------
__global__ __launch_bounds__(256, 2)
void conv_kernel(const float* __restrict__ content,
                 const float* __restrict__ conv_w,
                 const float* __restrict__ conv_b,
                 float* __restrict__ out) {
    const int bb = blockIdx.z;
    const int o0 = blockIdx.y * 64;
    const int t0 = blockIdx.x * 128;

    __shared__ float Ws[64][48];    // [oo][ii*3+tap]
    __shared__ float Xs[16][132];   // [ii][tt], tt=0 <-> t0-1, 130 used

    const int tid = threadIdx.x;
    const int tx = tid & 15;  // t dir (8 each)
    const int ty = tid >> 4;  // o dir (4 each)

    const int woo = tid >> 2;          // 0..63
    const int wc0 = (tid & 3) * 12;    // 0,12,24,36

    float acc[4][8];
#pragma unroll
    for (int i = 0; i < 4; i++)
#pragma unroll
        for (int j = 0; j < 8; j++) acc[i][j] = 0.f;

    for (int i0 = 0; i0 < 2 * D_; i0 += 16) {
        // weights: 48 contiguous floats per output channel row
        const float* wrow = conv_w + (size_t)(o0 + woo) * (2 * D_ * 3) + (size_t)i0 * 3 + wc0;
#pragma unroll
        for (int q = 0; q < 3; q++)
            *reinterpret_cast<float4*>(&Ws[woo][wc0 + q * 4]) =
                *reinterpret_cast<const float4*>(&wrow[q * 4]);

        // input tile with halo
        for (int idx = tid; idx < 16 * 130; idx += 256) {
            const int ii = idx / 130;
            const int tt = idx - ii * 130;
            const int t = t0 + tt - 1;
            const int gi = i0 + ii;
            float v = 0.f;
            if (t >= 0 && t < TC_) {
                v = (gi < D_) ? content[((size_t)bb * D_ + gi) * TC_ + t]
                              : g_wT[((size_t)bb * D_ + (gi - D_)) * TC_ + t];
            }
            Xs[ii][tt] = v;
        }
        __syncthreads();

#pragma unroll
        for (int ii = 0; ii < 16; ii++) {
            float xr[10];
#pragma unroll
            for (int q = 0; q < 10; q++) xr[q] = Xs[ii][tx * 8 + q];
#pragma unroll
            for (int i = 0; i < 4; i++) {
                const float w0 = Ws[ty * 4 + i][ii * 3 + 0];
                const float w1 = Ws[ty * 4 + i][ii * 3 + 1];
                const float w2 = Ws[ty * 4 + i][ii * 3 + 2];
#pragma unroll
                for (int j = 0; j < 8; j++) {
                    acc[i][j] = fmaf(w0, xr[j], acc[i][j]);
                    acc[i][j] = fmaf(w1, xr[j + 1], acc[i][j]);
                    acc[i][j] = fmaf(w2, xr[j + 2], acc[i][j]);
                }
            }
        }
        __syncthreads();
    }

#pragma unroll
    for (int i = 0; i < 4; i++) {
        const int o = o0 + ty * 4 + i;
        const float bv = __ldg(&conv_b[o]);
        float* orow = out + ((size_t)bb * TGT_ + o) * TC_ + t0 + tx * 8;
        float4 v0 = {acc[i][0] + bv, acc[i][1] + bv, acc[i][2] + bv, acc[i][3] + bv};
        float4 v1 = {acc[i][4] + bv, acc[i][5] + bv, acc[i][6] + bv, acc[i][7] + bv};
        *reinterpret_cast<float4*>(orow) = v0;
        *reinterpret_cast<float4*>(orow + 4) = v1;
    }
}

// ---------------------------------------------------------------------------
extern "C" void kernel_launch(void* const* d_in, const int* in_sizes, int n_in,
                              void* d_out, int out_size) {
    const float* content = (const float*)d_in[0];  // [8,256,2048]
    const float* emotion = (const float*)d_in[1];  // [8,256,2048]
    const float* conv_w  = (const float*)d_in[2];  // [256,512,3]
    const float* conv_b  = (const float*)d_in[3];  // [256]
    float* out = (float*)d_out;                    // [8,256,2048]

    dim3 g1(TE_ / 128, TC_ / 128, B_);
    gemm1_kernel<<<g1, 256>>>(content, emotion);

    softmax_kernel<<<B_ * TC_, 256>>>();

    dim3 g2(TC_ / 128, D_ / 64, B_);
    gemm2_kernel<<<g2, 256>>>(emotion);

    dim3 g3(TC_ / 128, TGT_ / 64, B_);
    conv_kernel<<<g3, 256>>>(content, conv_w, conv_b, out);
}

// round 8
// speedup vs baseline: 1.0500x; 1.0011x over previous
#include <cuda_runtime.h>
#include <math.h>

#define B_   8
#define D_   256
#define TC_  2048
#define TE_  2048
#define TGT_ 256

// Scratch (allocation-free rule: __device__ globals)
__device__ float g_attn[(size_t)B_ * TC_ * TE_];   // sim -> attn in place (134 MB)
__device__ float g_wT[(size_t)B_ * D_ * TC_];      // weighted_emo, stored [B, D, Tc] (16 MB)

// ---------------------------------------------------------------------------
// GEMM1: sim[b,t,s] = sum_d content[b,d,t] * emotion[b,d,s]
// content: [B, D, TC] row-major (t contiguous); emotion: [B, D, TE] (s contiguous)
// Classic 128x128x8 SGEMM, 256 threads, 8x8 per thread.
// ---------------------------------------------------------------------------
__global__ __launch_bounds__(256, 2)
void gemm1_kernel(const float* __restrict__ content,
                  const float* __restrict__ emotion) {
    const int bb = blockIdx.z;
    const int t0 = blockIdx.y * 128;
    const int s0 = blockIdx.x * 128;
    const float* A = content + (size_t)bb * D_ * TC_;
    const float* Bm = emotion + (size_t)bb * D_ * TE_;
    float* C = g_attn + (size_t)bb * TC_ * TE_;

    __shared__ float As[8][128];
    __shared__ float Bs[8][128];

    const int tid = threadIdx.x;
    const int tx = tid & 15;          // s dir
    const int ty = tid >> 4;          // t dir
    const int lrow = tid >> 5;        // 0..7
    const int lcol = (tid & 31) * 4;  // 0..124

    float acc[8][8];
#pragma unroll
    for (int i = 0; i < 8; i++)
#pragma unroll
        for (int j = 0; j < 8; j++) acc[i][j] = 0.f;

    for (int k0 = 0; k0 < D_; k0 += 8) {
        float4 a4 = *reinterpret_cast<const float4*>(&A[(size_t)(k0 + lrow) * TC_ + t0 + lcol]);
        float4 b4 = *reinterpret_cast<const float4*>(&Bm[(size_t)(k0 + lrow) * TE_ + s0 + lcol]);
        *reinterpret_cast<float4*>(&As[lrow][lcol]) = a4;
        *reinterpret_cast<float4*>(&Bs[lrow][lcol]) = b4;
        __syncthreads();
#pragma unroll
        for (int kk = 0; kk < 8; kk++) {
            float4 a0 = *reinterpret_cast<const float4*>(&As[kk][ty * 8]);
            float4 a1 = *reinterpret_cast<const float4*>(&As[kk][ty * 8 + 4]);
            float4 b0 = *reinterpret_cast<const float4*>(&Bs[kk][tx * 8]);
            float4 b1 = *reinterpret_cast<const float4*>(&Bs[kk][tx * 8 + 4]);
            float ra[8] = {a0.x, a0.y, a0.z, a0.w, a1.x, a1.y, a1.z, a1.w};
            float rb[8] = {b0.x, b0.y, b0.z, b0.w, b1.x, b1.y, b1.z, b1.w};
#pragma unroll
            for (int i = 0; i < 8; i++)
#pragma unroll
                for (int j = 0; j < 8; j++) acc[i][j] = fmaf(ra[i], rb[j], acc[i][j]);
        }
        __syncthreads();
    }

#pragma unroll
    for (int i = 0; i < 8; i++) {
        float* crow = &C[(size_t)(t0 + ty * 8 + i) * TE_ + s0 + tx * 8];
        float4 v0 = {acc[i][0], acc[i][1], acc[i][2], acc[i][3]};
        float4 v1 = {acc[i][4], acc[i][5], acc[i][6], acc[i][7]};
        *reinterpret_cast<float4*>(crow) = v0;
        *reinterpret_cast<float4*>(crow + 4) = v1;
    }
}

// ---------------------------------------------------------------------------
// Softmax over s (2048), with 1/16 logit scale, in place on g_attn.
// One block (256 threads) per row; each thread owns 8 consecutive elements.
// ---------------------------------------------------------------------------
__global__ __launch_bounds__(256)
void softmax_kernel() {
    const size_t r = blockIdx.x;
    float* row = g_attn + r * (size_t)TE_;
    const int tid = threadIdx.x;
    const int lane = tid & 31, wid = tid >> 5;

    float4 v0 = reinterpret_cast<float4*>(row)[tid * 2];
    float4 v1 = reinterpret_cast<float4*>(row)[tid * 2 + 1];
    float v[8] = {v0.x, v0.y, v0.z, v0.w, v1.x, v1.y, v1.z, v1.w};

    float m = v[0];
#pragma unroll
    for (int q = 1; q < 8; q++) m = fmaxf(m, v[q]);
#pragma unroll
    for (int o = 16; o > 0; o >>= 1) m = fmaxf(m, __shfl_xor_sync(0xffffffffu, m, o));

    __shared__ float smax[8];
    __shared__ float ssum[8];
    if (lane == 0) smax[wid] = m;
    __syncthreads();
    if (tid < 32) {
        float t = (lane < 8) ? smax[lane] : -INFINITY;
#pragma unroll
        for (int o = 4; o > 0; o >>= 1) t = fmaxf(t, __shfl_xor_sync(0xffffffffu, t, o));
        if (lane == 0) smax[0] = t;
    }
    __syncthreads();
    const float bm = smax[0];

    float s = 0.f;
#pragma unroll
    for (int q = 0; q < 8; q++) {
        v[q] = expf((v[q] - bm) * 0.0625f);
        s += v[q];
    }
#pragma unroll
    for (int o = 16; o > 0; o >>= 1) s += __shfl_xor_sync(0xffffffffu, s, o);
    if (lane == 0) ssum[wid] = s;
    __syncthreads();
    if (tid < 32) {
        float t = (lane < 8) ? ssum[lane] : 0.f;
#pragma unroll
        for (int o = 4; o > 0; o >>= 1) t += __shfl_xor_sync(0xffffffffu, t, o);
        if (lane == 0) ssum[0] = t;
    }
    __syncthreads();
    const float inv = 1.f / ssum[0];

    float4 o0 = {v[0] * inv, v[1] * inv, v[2] * inv, v[3] * inv};
    float4 o1 = {v[4] * inv, v[5] * inv, v[6] * inv, v[7] * inv};
    reinterpret_cast<float4*>(row)[tid * 2] = o0;
    reinterpret_cast<float4*>(row)[tid * 2 + 1] = o1;
}

// ---------------------------------------------------------------------------
// GEMM2: wT[b,d,t] = sum_s emotion[b,d,s] * attn[b,t,s]   ("NT" gemm)
// Tile: 64 (d) x 128 (t) x 16 (s). 256 threads, 4x8 per thread.
// ---------------------------------------------------------------------------
__global__ __launch_bounds__(256, 2)
void gemm2_kernel(const float* __restrict__ emotion) {
    const int bb = blockIdx.z;
    const int d0 = blockIdx.y * 64;
    const int t0 = blockIdx.x * 128;
    const float* E = emotion + (size_t)bb * D_ * TE_;
    const float* At = g_attn + (size_t)bb * TC_ * TE_;
    float* C = g_wT + (size_t)bb * D_ * TC_;

    __shared__ float As[16][68];   // [s][d], pad keeps rows 16B-aligned
    __shared__ float Bs[16][132];  // [s][t]

    const int tid = threadIdx.x;
    const int tx = tid & 15;   // t dir (8 each)
    const int ty = tid >> 4;   // d dir (4 each)

    const int add = tid >> 2;           // 0..63
    const int akq = (tid & 3) * 4;      // 0,4,8,12
    const int btt = tid >> 1;           // 0..127
    const int bkq = (tid & 1) * 8;      // 0 or 8

    float acc[4][8];
#pragma unroll
    for (int i = 0; i < 4; i++)
#pragma unroll
        for (int j = 0; j < 8; j++) acc[i][j] = 0.f;

    for (int s0 = 0; s0 < TE_; s0 += 16) {
        float4 a4 = *reinterpret_cast<const float4*>(&E[(size_t)(d0 + add) * TE_ + s0 + akq]);
        As[akq + 0][add] = a4.x;
        As[akq + 1][add] = a4.y;
        As[akq + 2][add] = a4.z;
        As[akq + 3][add] = a4.w;

        const float* brow = &At[(size_t)(t0 + btt) * TE_ + s0 + bkq];
        float4 b4a = *reinterpret_cast<const float4*>(brow);
        float4 b4b = *reinterpret_cast<const float4*>(brow + 4);
        Bs[bkq + 0][btt] = b4a.x;
        Bs[bkq + 1][btt] = b4a.y;
        Bs[bkq + 2][btt] = b4a.z;
        Bs[bkq + 3][btt] = b4a.w;
        Bs[bkq + 4][btt] = b4b.x;
        Bs[bkq + 5][btt] = b4b.y;
        Bs[bkq + 6][btt] = b4b.z;
        Bs[bkq + 7][btt] = b4b.w;
        __syncthreads();

#pragma unroll
        for (int kk = 0; kk < 16; kk++) {
            float4 ra4 = *reinterpret_cast<const float4*>(&As[kk][ty * 4]);
            float4 rb0 = *reinterpret_cast<const float4*>(&Bs[kk][tx * 8]);
            float4 rb1 = *reinterpret_cast<const float4*>(&Bs[kk][tx * 8 + 4]);
            float ra[4] = {ra4.x, ra4.y, ra4.z, ra4.w};
            float rb[8] = {rb0.x, rb0.y, rb0.z, rb0.w, rb1.x, rb1.y, rb1.z, rb1.w};
#pragma unroll
            for (int i = 0; i < 4; i++)
#pragma unroll
                for (int j = 0; j < 8; j++) acc[i][j] = fmaf(ra[i], rb[j], acc[i][j]);
        }
        __syncthreads();
    }

#pragma unroll
    for (int i = 0; i < 4; i++) {
        float* crow = &C[(size_t)(d0 + ty * 4 + i) * TC_ + t0 + tx * 8];
        float4 v0 = {acc[i][0], acc[i][1], acc[i][2], acc[i][3]};
        float4 v1 = {acc[i][4], acc[i][5], acc[i][6], acc[i][7]};
        *reinterpret_cast<float4*>(crow) = v0;
        *reinterpret_cast<float4*>(crow + 4) = v1;
    }
}

// ---------------------------------------------------------------------------
// Conv1d k=3 pad=1: out[b,o,t] = bias[o] + sum_{i<512} sum_tap w[o,i,tap]*x[b,i,t+tap-1]
// x[b,i,t] = (i<256) ? content[b,i,t] : g_wT[b,i-256,t]  (virtual concat)
// Tile: 64 (o) x 128 (t), K-chunks of 16 channels.
// ---------------------------------------------------------------------------
__global__ __launch_bounds__(256, 2)
void conv_kernel(const float* __restrict__ content,
                 const float* __restrict__ conv_w,
                 const float* __restrict__ conv_b,
                 float* __restrict__ out) {
    const int bb = blockIdx.z;
    const int o0 = blockIdx.y * 64;
    const int t0 = blockIdx.x * 128;

    __shared__ float Ws[64][48];    // [oo][ii*3+tap]
    __shared__ float Xs[16][132];   // [ii][tt], tt=0 <-> t0-1, 130 used

    const int tid = threadIdx.x;
    const int tx = tid & 15;  // t dir (8 each)
    const int ty = tid >> 4;  // o dir (4 each)

    const int woo = tid >> 2;          // 0..63
    const int wc0 = (tid & 3) * 12;    // 0,12,24,36

    float acc[4][8];
#pragma unroll
    for (int i = 0; i < 4; i++)
#pragma unroll
        for (int j = 0; j < 8; j++) acc[i][j] = 0.f;

    for (int i0 = 0; i0 < 2 * D_; i0 += 16) {
        // weights: 48 contiguous floats per output channel row
        const float* wrow = conv_w + (size_t)(o0 + woo) * (2 * D_ * 3) + (size_t)i0 * 3 + wc0;
#pragma unroll
        for (int q = 0; q < 3; q++)
            *reinterpret_cast<float4*>(&Ws[woo][wc0 + q * 4]) =
                *reinterpret_cast<const float4*>(&wrow[q * 4]);

        // input tile with halo
        for (int idx = tid; idx < 16 * 130; idx += 256) {
            const int ii = idx / 130;
            const int tt = idx - ii * 130;
            const int t = t0 + tt - 1;
            const int gi = i0 + ii;
            float v = 0.f;
            if (t >= 0 && t < TC_) {
                v = (gi < D_) ? content[((size_t)bb * D_ + gi) * TC_ + t]
                              : g_wT[((size_t)bb * D_ + (gi - D_)) * TC_ + t];
            }
            Xs[ii][tt] = v;
        }
        __syncthreads();

#pragma unroll
        for (int ii = 0; ii < 16; ii++) {
            float xr[10];
#pragma unroll
            for (int q = 0; q < 10; q++) xr[q] = Xs[ii][tx * 8 + q];
#pragma unroll
            for (int i = 0; i < 4; i++) {
                const float w0 = Ws[ty * 4 + i][ii * 3 + 0];
                const float w1 = Ws[ty * 4 + i][ii * 3 + 1];
                const float w2 = Ws[ty * 4 + i][ii * 3 + 2];
#pragma unroll
                for (int j = 0; j < 8; j++) {
                    acc[i][j] = fmaf(w0, xr[j], acc[i][j]);
                    acc[i][j] = fmaf(w1, xr[j + 1], acc[i][j]);
                    acc[i][j] = fmaf(w2, xr[j + 2], acc[i][j]);
                }
            }
        }
        __syncthreads();
    }

#pragma unroll
    for (int i = 0; i < 4; i++) {
        const int o = o0 + ty * 4 + i;
        const float bv = __ldg(&conv_b[o]);
        float* orow = out + ((size_t)bb * TGT_ + o) * TC_ + t0 + tx * 8;
        float4 v0 = {acc[i][0] + bv, acc[i][1] + bv, acc[i][2] + bv, acc[i][3] + bv};
        float4 v1 = {acc[i][4] + bv, acc[i][5] + bv, acc[i][6] + bv, acc[i][7] + bv};
        *reinterpret_cast<float4*>(orow) = v0;
        *reinterpret_cast<float4*>(orow + 4) = v1;
    }
}

// ---------------------------------------------------------------------------
extern "C" void kernel_launch(void* const* d_in, const int* in_sizes, int n_in,
                              void* d_out, int out_size) {
    const float* content = (const float*)d_in[0];  // [8,256,2048]
    const float* emotion = (const float*)d_in[1];  // [8,256,2048]
    const float* conv_w  = (const float*)d_in[2];  // [256,512,3]
    const float* conv_b  = (const float*)d_in[3];  // [256]
    float* out = (float*)d_out;                    // [8,256,2048]

    dim3 g1(TE_ / 128, TC_ / 128, B_);
    gemm1_kernel<<<g1, 256>>>(content, emotion);

    softmax_kernel<<<B_ * TC_, 256>>>();

    dim3 g2(TC_ / 128, D_ / 64, B_);
    gemm2_kernel<<<g2, 256>>>(emotion);

    dim3 g3(TC_ / 128, TGT_ / 64, B_);
    conv_kernel<<<g3, 256>>>(content, conv_w, conv_b, out);
}